// round 1
// baseline (speedup 1.0000x reference)
#include <cuda_runtime.h>
#include <cstdint>
#include <math.h>

// Problem constants
#define BATCH 32
#define NQ    1024
#define NK    2048
#define DMODEL 256

// GEMM tiling
#define BM 128
#define BN 128
#define BK 32
#define LDSA 36                    // smem row stride (floats), conflict-free
#define TILE_F (128 * LDSA)        // floats per (A or B) tile buffer
#define BUF_STRIDE (2 * TILE_F)    // floats per double-buffer stage (A+B)
#define SMEM_BYTES (2 * BUF_STRIDE * 4)

// Scratch (static device memory — allocation-free per harness rules)
__device__ float g_q [BATCH * NQ * DMODEL];          // [b*NQ + q][d]   (tf32-rounded)
__device__ float g_k [BATCH * NK * DMODEL];          // [b*NK + k][d]   (tf32-rounded)
__device__ float g_vT[BATCH * DMODEL * NK];          // [b][d][k]       (tf32-rounded, bias added)

__device__ __forceinline__ uint32_t f2tf32(float x) {
    uint32_t r;
    asm("cvt.rna.tf32.f32 %0, %1;" : "=r"(r) : "f"(x));
    return r;
}

__device__ __forceinline__ void mma_tf32(float c[4], const uint32_t a[4], const uint32_t b[2]) {
    asm("mma.sync.aligned.m16n8k8.row.col.f32.tf32.tf32.f32 "
        "{%0,%1,%2,%3}, {%4,%5,%6,%7}, {%8,%9}, {%0,%1,%2,%3};"
        : "+f"(c[0]), "+f"(c[1]), "+f"(c[2]), "+f"(c[3])
        : "r"(a[0]), "r"(a[1]), "r"(a[2]), "r"(a[3]), "r"(b[0]), "r"(b[1]));
}

__device__ __forceinline__ void cp_async16(float* smem, const float* gmem) {
    uint32_t s = (uint32_t)__cvta_generic_to_shared(smem);
    asm volatile("cp.async.cg.shared.global [%0], [%1], 16;" :: "r"(s), "l"(gmem) : "memory");
}
__device__ __forceinline__ void cp_commit() { asm volatile("cp.async.commit_group;" ::: "memory"); }
template<int N> __device__ __forceinline__ void cp_wait() {
    asm volatile("cp.async.wait_group %0;" :: "n"(N) : "memory");
}

// Issue cp.asyncs for one 128x32 A tile and one 128x32 B tile (both [rows][K] layout).
__device__ __forceinline__ void load_tile(const float* a, long long lda,
                                          const float* b, long long ldb,
                                          float* sA, float* sB) {
#pragma unroll
    for (int r = 0; r < 128; r += 32) {
        cp_async16(sA + r * LDSA, a + (long long)r * lda);
        cp_async16(sB + r * LDSA, b + (long long)r * ldb);
    }
    cp_commit();
}

// NT GEMM mainloop: acc[m][n] += sum_k A[m0+m][k] * B[n0+n][k]
// A: [M][lda] row-major, B: [N][ldb] row-major ("NT" — both K-contiguous).
// CTA tile 128x128, 8 warps (4 M x 2 N), warp tile 32x64 via m16n8k8 tf32 mma.
template<bool CVT>
__device__ __forceinline__ void gemm_loop(const float* __restrict__ A, long long lda,
                                          const float* __restrict__ B, long long ldb,
                                          int K, int m0, int n0,
                                          float (&acc)[2][8][4], float* smem) {
    const int tid  = threadIdx.x;
    const int warp = tid >> 5, lane = tid & 31;
    const int wm = warp >> 1, wn = warp & 1;
    const int g  = lane >> 2, tg = lane & 3;
    const int lrow = tid >> 3;            // 0..31
    const int lcol = (tid & 7) << 2;      // 0,4,...,28

    const float* Ag = A + (long long)(m0 + lrow) * lda + lcol;
    const float* Bg = B + (long long)(n0 + lrow) * ldb + lcol;
    float* sA0 = smem + lrow * LDSA + lcol;
    float* sB0 = smem + TILE_F + lrow * LDSA + lcol;

    const int kt = K >> 5;   // K / 32

    load_tile(Ag, lda, Bg, ldb, sA0, sB0);

    for (int it = 0; it < kt; ++it) {
        int nxt = (it + 1) & 1;
        if (it + 1 < kt) {
            load_tile(Ag + (it + 1) * BK, lda, Bg + (it + 1) * BK, ldb,
                      sA0 + nxt * BUF_STRIDE, sB0 + nxt * BUF_STRIDE);
            cp_wait<1>();
        } else {
            cp_wait<0>();
        }
        __syncthreads();

        const float* cA = smem + (it & 1) * BUF_STRIDE;
        const float* cB = smem + (it & 1) * BUF_STRIDE + TILE_F;

#pragma unroll
        for (int kk = 0; kk < BK; kk += 8) {
            uint32_t af[2][4];
            uint32_t bf[8][2];
#pragma unroll
            for (int mi = 0; mi < 2; mi++) {
                const float* base = cA + (wm * 32 + mi * 16 + g) * LDSA + kk + tg;
                float x0 = base[0];
                float x1 = base[8 * LDSA];
                float x2 = base[4];
                float x3 = base[8 * LDSA + 4];
                af[mi][0] = CVT ? f2tf32(x0) : __float_as_uint(x0);
                af[mi][1] = CVT ? f2tf32(x1) : __float_as_uint(x1);
                af[mi][2] = CVT ? f2tf32(x2) : __float_as_uint(x2);
                af[mi][3] = CVT ? f2tf32(x3) : __float_as_uint(x3);
            }
#pragma unroll
            for (int ni = 0; ni < 8; ni++) {
                const float* base = cB + (wn * 64 + ni * 8 + g) * LDSA + kk + tg;
                float y0 = base[0];
                float y1 = base[4];
                bf[ni][0] = CVT ? f2tf32(y0) : __float_as_uint(y0);
                bf[ni][1] = CVT ? f2tf32(y1) : __float_as_uint(y1);
            }
#pragma unroll
            for (int mi = 0; mi < 2; mi++)
#pragma unroll
                for (int ni = 0; ni < 8; ni++)
                    mma_tf32(acc[mi][ni], af[mi], bf[ni]);
        }
        __syncthreads();
    }
}

// ---------------- Projection kernels ----------------
// C[m][n] = sum_i X[m][i] * W[n][i] + bias[n], stored tf32-rounded.
// MODE 0: -> g_q  (m over B*NQ)
// MODE 1: -> g_k  (m over B*NK)
// MODE 2: -> g_vT transposed: vT[b][n][m % NK]  (m over B*NK)
template<int MODE>
__global__ void __launch_bounds__(256) proj_kernel(const float* __restrict__ X,
                                                   const float* __restrict__ W,
                                                   const float* __restrict__ bvec) {
    extern __shared__ float smem[];
    float acc[2][8][4] = {};
    const int m0 = blockIdx.x * BM, n0 = blockIdx.y * BN;
    gemm_loop<true>(X, DMODEL, W, DMODEL, DMODEL, m0, n0, acc, smem);

    const int tid = threadIdx.x, warp = tid >> 5, lane = tid & 31;
    const int wm = warp >> 1, wn = warp & 1, g = lane >> 2, tg = lane & 3;

#pragma unroll
    for (int mi = 0; mi < 2; mi++) {
#pragma unroll
        for (int half = 0; half < 2; half++) {
            int r = m0 + wm * 32 + mi * 16 + g + half * 8;
#pragma unroll
            for (int ni = 0; ni < 8; ni++) {
#pragma unroll
                for (int cj = 0; cj < 2; cj++) {
                    int c = n0 + wn * 64 + ni * 8 + tg * 2 + cj;
                    float v = acc[mi][ni][half * 2 + cj] + bvec[c];
                    float t = __uint_as_float(f2tf32(v));
                    if (MODE == 0) {
                        g_q[(long long)r * DMODEL + c] = t;
                    } else if (MODE == 1) {
                        g_k[(long long)r * DMODEL + c] = t;
                    } else {
                        long long bidx = r >> 11;               // NK = 2048
                        long long idx = (bidx * DMODEL + c) * NK + (r & (NK - 1));
                        g_vT[idx] = t;
                    }
                }
            }
        }
    }
}

// ---------------- Logits kernel ----------------
// w[b][q][k] = (q . k)/16 + bias, masked -> -1e9 (raw logits; softmax pass follows)
__global__ void __launch_bounds__(256) logits_kernel(const float* __restrict__ bias,
                                                     const int* __restrict__ qmask,
                                                     const int* __restrict__ kmask,
                                                     float* __restrict__ w) {
    extern __shared__ float smem[];
    const int b = blockIdx.z;
    const int m0 = blockIdx.x * BM, n0 = blockIdx.y * BN;
    float acc[2][8][4] = {};
    gemm_loop<false>(g_q + (long long)b * NQ * DMODEL, DMODEL,
                     g_k + (long long)b * NK * DMODEL, DMODEL,
                     DMODEL, m0, n0, acc, smem);

    const float* bb = bias + (long long)b * NQ * NK;
    const int* qm = qmask + b * NQ;
    const int* km = kmask + b * NK;
    float* wb = w + (long long)b * NQ * NK;

    const int tid = threadIdx.x, warp = tid >> 5, lane = tid & 31;
    const int wm = warp >> 1, wn = warp & 1, g = lane >> 2, tg = lane & 3;

#pragma unroll
    for (int mi = 0; mi < 2; mi++) {
#pragma unroll
        for (int half = 0; half < 2; half++) {
            int r = m0 + wm * 32 + mi * 16 + g + half * 8;
            int qmr = qm[r];
#pragma unroll
            for (int ni = 0; ni < 8; ni++) {
#pragma unroll
                for (int cj = 0; cj < 2; cj++) {
                    int c = n0 + wn * 64 + ni * 8 + tg * 2 + cj;
                    float l = acc[mi][ni][half * 2 + cj] * 0.0625f
                              + bb[(long long)r * NK + c];
                    wb[(long long)r * NK + c] = (qmr && km[c]) ? l : -1e9f;
                }
            }
        }
    }
}

// ---------------- Softmax kernel ----------------
// One CTA (256 thr) per row of 2048. In-place; output tf32-rounded (feeds out GEMM).
__global__ void __launch_bounds__(256) softmax_kernel(float* __restrict__ w) {
    __shared__ float red[8];
    float* p = w + (long long)blockIdx.x * NK;
    const int tid = threadIdx.x;

    float4 u0 = reinterpret_cast<float4*>(p)[tid * 2];
    float4 u1 = reinterpret_cast<float4*>(p)[tid * 2 + 1];
    float x[8] = {u0.x, u0.y, u0.z, u0.w, u1.x, u1.y, u1.z, u1.w};

    float mx = x[0];
#pragma unroll
    for (int i = 1; i < 8; i++) mx = fmaxf(mx, x[i]);
#pragma unroll
    for (int o = 16; o; o >>= 1) mx = fmaxf(mx, __shfl_xor_sync(0xffffffffu, mx, o));
    if ((tid & 31) == 0) red[tid >> 5] = mx;
    __syncthreads();
    float m2 = red[0];
#pragma unroll
    for (int i = 1; i < 8; i++) m2 = fmaxf(m2, red[i]);
    __syncthreads();

    float e[8], s = 0.f;
#pragma unroll
    for (int i = 0; i < 8; i++) { e[i] = expf(x[i] - m2); s += e[i]; }
#pragma unroll
    for (int o = 16; o; o >>= 1) s += __shfl_xor_sync(0xffffffffu, s, o);
    if ((tid & 31) == 0) red[tid >> 5] = s;
    __syncthreads();
    float tot = red[0];
#pragma unroll
    for (int i = 1; i < 8; i++) tot += red[i];
    float inv = 1.0f / tot;

    float4 o0, o1;
    o0.x = __uint_as_float(f2tf32(e[0] * inv));
    o0.y = __uint_as_float(f2tf32(e[1] * inv));
    o0.z = __uint_as_float(f2tf32(e[2] * inv));
    o0.w = __uint_as_float(f2tf32(e[3] * inv));
    o1.x = __uint_as_float(f2tf32(e[4] * inv));
    o1.y = __uint_as_float(f2tf32(e[5] * inv));
    o1.z = __uint_as_float(f2tf32(e[6] * inv));
    o1.w = __uint_as_float(f2tf32(e[7] * inv));
    reinterpret_cast<float4*>(p)[tid * 2]     = o0;
    reinterpret_cast<float4*>(p)[tid * 2 + 1] = o1;
}

// ---------------- Output GEMM ----------------
// out[b][q][d] = sum_k w[b][q][k] * vT[b][d][k]   (K = 2048)
__global__ void __launch_bounds__(256) out_kernel(const float* __restrict__ w,
                                                  float* __restrict__ out) {
    extern __shared__ float smem[];
    const int b = blockIdx.z;
    const int m0 = blockIdx.x * BM, n0 = blockIdx.y * BN;
    float acc[2][8][4] = {};
    gemm_loop<false>(w + (long long)b * NQ * NK, NK,
                     g_vT + (long long)b * DMODEL * NK, NK,
                     NK, m0, n0, acc, smem);

    float* ob = out + (long long)b * NQ * DMODEL;
    const int tid = threadIdx.x, warp = tid >> 5, lane = tid & 31;
    const int wm = warp >> 1, wn = warp & 1, g = lane >> 2, tg = lane & 3;

#pragma unroll
    for (int mi = 0; mi < 2; mi++) {
#pragma unroll
        for (int half = 0; half < 2; half++) {
            int r = m0 + wm * 32 + mi * 16 + g + half * 8;
#pragma unroll
            for (int ni = 0; ni < 8; ni++) {
#pragma unroll
                for (int cj = 0; cj < 2; cj++) {
                    int c = n0 + wn * 64 + ni * 8 + tg * 2 + cj;
                    ob[(long long)r * DMODEL + c] = acc[mi][ni][half * 2 + cj];
                }
            }
        }
    }
}

extern "C" void kernel_launch(void* const* d_in, const int* in_sizes, int n_in,
                              void* d_out, int out_size) {
    (void)in_sizes; (void)n_in; (void)out_size;
    const float* query = (const float*)d_in[0];
    const float* key   = (const float*)d_in[1];
    const float* value = (const float*)d_in[2];
    const int*   qmask = (const int*)d_in[3];
    const int*   kmask = (const int*)d_in[4];
    const float* bias  = (const float*)d_in[5];
    const float* Wq = (const float*)d_in[6];
    const float* bq = (const float*)d_in[7];
    const float* Wk = (const float*)d_in[8];
    const float* bk = (const float*)d_in[9];
    const float* Wv = (const float*)d_in[10];
    const float* bv = (const float*)d_in[11];

    float* out = (float*)d_out;                                   // (B, NQ, D)
    float* w   = out + (size_t)BATCH * NQ * DMODEL;               // (B, NQ, NK)

    cudaFuncSetAttribute((const void*)proj_kernel<0>, cudaFuncAttributeMaxDynamicSharedMemorySize, SMEM_BYTES);
    cudaFuncSetAttribute((const void*)proj_kernel<1>, cudaFuncAttributeMaxDynamicSharedMemorySize, SMEM_BYTES);
    cudaFuncSetAttribute((const void*)proj_kernel<2>, cudaFuncAttributeMaxDynamicSharedMemorySize, SMEM_BYTES);
    cudaFuncSetAttribute((const void*)logits_kernel,  cudaFuncAttributeMaxDynamicSharedMemorySize, SMEM_BYTES);
    cudaFuncSetAttribute((const void*)out_kernel,     cudaFuncAttributeMaxDynamicSharedMemorySize, SMEM_BYTES);

    // Projections: Q (M=32768), K (M=65536), V (M=65536, transposed store)
    proj_kernel<0><<<dim3(BATCH * NQ / BM, DMODEL / BN, 1), 256, SMEM_BYTES>>>(query, Wq, bq);
    proj_kernel<1><<<dim3(BATCH * NK / BM, DMODEL / BN, 1), 256, SMEM_BYTES>>>(key,   Wk, bk);
    proj_kernel<2><<<dim3(BATCH * NK / BM, DMODEL / BN, 1), 256, SMEM_BYTES>>>(value, Wv, bv);

    // Logits (+bias, +mask) into weights region
    logits_kernel<<<dim3(NQ / BM, NK / BN, BATCH), 256, SMEM_BYTES>>>(bias, qmask, kmask, w);

    // Row softmax in place
    softmax_kernel<<<BATCH * NQ, 256>>>(w);

    // out = weights @ v
    out_kernel<<<dim3(NQ / BM, DMODEL / BN, BATCH), 256, SMEM_BYTES>>>(w, out);
}